// round 4
// baseline (speedup 1.0000x reference)
#include <cuda_runtime.h>
#include <math.h>

#define NN 4096
#define FF 128
#define DD 64
#define KH 3

// ---------------- scratch (device globals; no allocations allowed) ----------
__device__ float g_E[NN * DD];        // X @ W_emb
__device__ float g_XW[KH * NN * DD];  // per-hop projections
__device__ float g_C[KH * NN * DD];   // C_k = A_k @ Y_k
__device__ float g_dinv[KH * NN];     // deg^{-1/2}
__device__ float g_S[DD];             // colsum(E)
__device__ float g_M[KH * DD * DD];   // M_k = E^T @ Y_k

__device__ __forceinline__ unsigned long long ffma2(unsigned long long a,
                                                    unsigned long long b,
                                                    unsigned long long c) {
    unsigned long long d;
    asm("fma.rn.f32x2 %0, %1, %2, %3;" : "=l"(d) : "l"(a), "l"(b), "l"(c));
    return d;
}

// ---------------- zero the atomic accumulators ------------------------------
__global__ void zero_kernel() {
    int t = blockIdx.x * blockDim.x + threadIdx.x;
    if (t < DD) g_S[t] = 0.f;
    if (t < KH * DD * DD) g_M[t] = 0.f;
}

// ---------------- E = X @ W_emb, XW[k] = X @ W_hops[k] ----------------------
// grid (256, 4), block 256. blockIdx.y: 0 -> W_emb, 1..3 -> hops.
__global__ void proj_kernel(const float* __restrict__ X,
                            const float* __restrict__ Wemb,
                            const float* __restrict__ Whops) {
    __shared__ float Xs[16][FF + 1];
    const int rb = blockIdx.x;
    const int m = blockIdx.y;
    const float* W = (m == 0) ? Wemb : (Whops + (size_t)(m - 1) * FF * DD);
    float* Out = (m == 0) ? g_E : (g_XW + (size_t)(m - 1) * NN * DD);
    const int t = threadIdx.x;

    #pragma unroll
    for (int i = 0; i < 2; i++) {
        int idx = t + 256 * i;            // 512 float4s = 16x128
        int row = idx >> 5;
        int c4 = idx & 31;
        float4 v = *reinterpret_cast<const float4*>(X + (size_t)(rb * 16 + row) * FF + c4 * 4);
        Xs[row][c4 * 4 + 0] = v.x; Xs[row][c4 * 4 + 1] = v.y;
        Xs[row][c4 * 4 + 2] = v.z; Xs[row][c4 * 4 + 3] = v.w;
    }
    __syncthreads();

    const int c = t & 63;
    const int rq = t >> 6;                // 4 rows per thread
    float acc[4] = {0.f, 0.f, 0.f, 0.f};
    for (int f = 0; f < FF; f++) {
        float w = __ldg(W + (size_t)f * DD + c);
        #pragma unroll
        for (int r = 0; r < 4; r++) acc[r] += Xs[rq * 4 + r][f] * w;
    }
    #pragma unroll
    for (int r = 0; r < 4; r++)
        Out[(size_t)(rb * 16 + rq * 4 + r) * DD + c] = acc[r];
}

// ---------------- S = colsum(E). grid 32, block 256 -------------------------
__global__ void colsum_kernel() {
    __shared__ float red[4][DD];
    const int t = threadIdx.x;
    const int b = blockIdx.x;
    const int c = t & 63, g = t >> 6;
    float acc = 0.f;
    for (int r = 0; r < 32; r++)
        acc += g_E[(size_t)(b * 128 + g * 32 + r) * DD + c];
    red[g][c] = acc;
    __syncthreads();
    if (t < DD)
        atomicAdd(&g_S[t], red[0][t] + red[1][t] + red[2][t] + red[3][t]);
}

// ---------------- dinv[k][i] = (rowsum(A_k)[i] + alpha*E[i].S)^(-1/2) -------
// grid KH*NN, block 256. One block per (k, row).
__global__ void deg_kernel(const float* __restrict__ A,
                           const float* __restrict__ alpha_p) {
    __shared__ float wsum[8];
    __shared__ float dsum[2];
    const int bid = blockIdx.x;           // k*NN + i
    const int i = bid & (NN - 1);
    const float* Arow = A + (size_t)bid * NN;
    const int t = threadIdx.x;

    float acc = 0.f;
    #pragma unroll
    for (int j = 0; j < 4; j++) {
        float4 v = *reinterpret_cast<const float4*>(Arow + (size_t)(t + 256 * j) * 4);
        acc += (v.x + v.y) + (v.z + v.w);
    }
    #pragma unroll
    for (int o = 16; o > 0; o >>= 1) acc += __shfl_down_sync(0xffffffffu, acc, o);
    if ((t & 31) == 0) wsum[t >> 5] = acc;
    __syncthreads();
    if (t < 64) {
        float p = g_E[(size_t)i * DD + t] * g_S[t];
        #pragma unroll
        for (int o = 16; o > 0; o >>= 1) p += __shfl_down_sync(0xffffffffu, p, o);
        if ((t & 31) == 0) dsum[t >> 5] = p;
    }
    __syncthreads();
    if (t == 0) {
        float rs = 0.f;
        #pragma unroll
        for (int w = 0; w < 8; w++) rs += wsum[w];
        float deg = rs + __ldg(alpha_p) * (dsum[0] + dsum[1]);
        g_dinv[bid] = 1.0f / sqrtf(deg);
    }
}

// ---------------- M_k = E^T @ (d_k . XW_k)  (64x64 each) --------------------
// grid (64, KH): 64 chunks of 64 rows. block 256.
__global__ void mmat_kernel() {
    __shared__ float Es[64][DD];
    __shared__ float Ys[64][DD];
    const int k = blockIdx.y;
    const int base = blockIdx.x * 64;
    const int t = threadIdx.x;

    #pragma unroll
    for (int i = 0; i < 4; i++) {
        int idx = t + 256 * i;            // 1024 float4s
        int row = idx >> 4;
        int c4 = idx & 15;
        float4 e = *reinterpret_cast<const float4*>(g_E + (size_t)(base + row) * DD + c4 * 4);
        *reinterpret_cast<float4*>(&Es[row][c4 * 4]) = e;
        float dv = g_dinv[(size_t)k * NN + base + row];
        float4 xw = *reinterpret_cast<const float4*>(g_XW + ((size_t)k * NN + base + row) * DD + c4 * 4);
        xw.x *= dv; xw.y *= dv; xw.z *= dv; xw.w *= dv;
        *reinterpret_cast<float4*>(&Ys[row][c4 * 4]) = xw;
    }
    __syncthreads();

    const int t1 = t >> 4, t2 = t & 15;
    float acc[4][4] = {};
    for (int j = 0; j < 64; j++) {
        float4 e = *reinterpret_cast<const float4*>(&Es[j][t1 * 4]);
        float4 y = *reinterpret_cast<const float4*>(&Ys[j][t2 * 4]);
        float ea[4] = {e.x, e.y, e.z, e.w};
        float ya[4] = {y.x, y.y, y.z, y.w};
        #pragma unroll
        for (int a = 0; a < 4; a++)
            #pragma unroll
            for (int b = 0; b < 4; b++) acc[a][b] += ea[a] * ya[b];
    }
    #pragma unroll
    for (int a = 0; a < 4; a++)
        #pragma unroll
        for (int b = 0; b < 4; b++)
            atomicAdd(&g_M[(size_t)k * DD * DD + (t1 * 4 + a) * DD + t2 * 4 + b], acc[a][b]);
}

// ---------------- C_k = A_k @ Y_k  (main matmul, f32x2) ---------------------
// grid (128, KH), block 128. Tile 32(M) x 64(N) x 32(K).
// Accumulators are row-paired f32x2; A transposed in smem (aligned LDS.128
// yields two row-pairs), Y duplicated in smem so column loads are LDS.128.
__global__ void __launch_bounds__(128) spmm_kernel(const float* __restrict__ A) {
    __shared__ float Ast[32][32];      // [kcol][row]
    __shared__ float Ysd[32][128];     // [kcol][2*col] duplicated
    const int k = blockIdx.y;
    const int r0 = blockIdx.x * 32;
    const int t = threadIdx.x;
    const int tr = t >> 4;             // 0..7  -> rows 4tr..4tr+3
    const int tc = t & 15;             // 0..15 -> cols 4tc..4tc+3
    const float* Ab = A + ((size_t)k * NN + r0) * NN;
    const float* XWk = g_XW + (size_t)k * NN * DD;
    const float* dk = g_dinv + (size_t)k * NN;

    unsigned long long acc[2][4];
    #pragma unroll
    for (int p = 0; p < 2; p++)
        #pragma unroll
        for (int cc = 0; cc < 4; cc++) acc[p][cc] = 0ull;

    const int lrow = t >> 2;           // 0..31
    const int lq = t & 3;              // 8-float segment of the row

    for (int tk = 0; tk < NN / 32; tk++) {
        const int kk0 = tk * 32;
        __syncthreads();
        // A tile 32x32 -> transposed
        {
            const float* src = Ab + (size_t)lrow * NN + kk0 + lq * 8;
            #pragma unroll
            for (int i = 0; i < 2; i++) {
                float4 v = *reinterpret_cast<const float4*>(src + i * 4);
                int kc = lq * 8 + i * 4;
                Ast[kc + 0][lrow] = v.x;
                Ast[kc + 1][lrow] = v.y;
                Ast[kc + 2][lrow] = v.z;
                Ast[kc + 3][lrow] = v.w;
            }
        }
        // Y tile 32x64, scaled by dinv, duplicated per column
        {
            #pragma unroll
            for (int i = 0; i < 4; i++) {
                int idx = t + 128 * i;     // 512 float4s
                int row = idx >> 4;
                int c4 = idx & 15;
                float dv = dk[kk0 + row];
                float4 v = *reinterpret_cast<const float4*>(XWk + (size_t)(kk0 + row) * DD + c4 * 4);
                v.x *= dv; v.y *= dv; v.z *= dv; v.w *= dv;
                float4 d0 = make_float4(v.x, v.x, v.y, v.y);
                float4 d1 = make_float4(v.z, v.z, v.w, v.w);
                *reinterpret_cast<float4*>(&Ysd[row][8 * c4 + 0]) = d0;
                *reinterpret_cast<float4*>(&Ysd[row][8 * c4 + 4]) = d1;
            }
        }
        __syncthreads();
        #pragma unroll 8
        for (int kk = 0; kk < 32; kk++) {
            const ulonglong2 av  = *reinterpret_cast<const ulonglong2*>(&Ast[kk][4 * tr]);
            const ulonglong2 y01 = *reinterpret_cast<const ulonglong2*>(&Ysd[kk][8 * tc]);
            const ulonglong2 y23 = *reinterpret_cast<const ulonglong2*>(&Ysd[kk][8 * tc + 4]);
            acc[0][0] = ffma2(av.x, y01.x, acc[0][0]);
            acc[0][1] = ffma2(av.x, y01.y, acc[0][1]);
            acc[0][2] = ffma2(av.x, y23.x, acc[0][2]);
            acc[0][3] = ffma2(av.x, y23.y, acc[0][3]);
            acc[1][0] = ffma2(av.y, y01.x, acc[1][0]);
            acc[1][1] = ffma2(av.y, y01.y, acc[1][1]);
            acc[1][2] = ffma2(av.y, y23.x, acc[1][2]);
            acc[1][3] = ffma2(av.y, y23.y, acc[1][3]);
        }
    }
    // store: acc lo half = even row of the pair, hi half = odd row
    float* Cb = g_C + ((size_t)k * NN + r0) * DD;
    #pragma unroll
    for (int p = 0; p < 2; p++) {
        float2 v0 = *reinterpret_cast<float2*>(&acc[p][0]);
        float2 v1 = *reinterpret_cast<float2*>(&acc[p][1]);
        float2 v2 = *reinterpret_cast<float2*>(&acc[p][2]);
        float2 v3 = *reinterpret_cast<float2*>(&acc[p][3]);
        int rowA = 4 * tr + 2 * p;
        float4 ra = make_float4(v0.x, v1.x, v2.x, v3.x);
        float4 rb = make_float4(v0.y, v1.y, v2.y, v3.y);
        *reinterpret_cast<float4*>(Cb + (size_t)rowA * DD + 4 * tc) = ra;
        *reinterpret_cast<float4*>(Cb + (size_t)(rowA + 1) * DD + 4 * tc) = rb;
    }
}

// ---------------- out = relu( sum_k dinv_k[i] * (C_k + alpha * E @ M_k) ) ---
// grid 1024 (4 rows each), block 256.
__global__ void final_kernel(const float* __restrict__ alpha_p,
                             float* __restrict__ out) {
    __shared__ float Ms[DD][DD];
    __shared__ float Es[4][DD];
    const int b = blockIdx.x;
    const int t = threadIdx.x;
    const int ti = t >> 6, c = t & 63;
    const int i = b * 4 + ti;
    Es[ti][c] = g_E[(size_t)i * DD + c];
    const float alpha = __ldg(alpha_p);

    float acc = 0.f;
    for (int k = 0; k < KH; k++) {
        __syncthreads();
        #pragma unroll
        for (int q = 0; q < 16; q++) {
            int idx = t + 256 * q;        // 4096 floats
            Ms[idx >> 6][idx & 63] = g_M[(size_t)k * DD * DD + idx];
        }
        __syncthreads();
        float dotm = 0.f;
        #pragma unroll 8
        for (int c1 = 0; c1 < DD; c1++) dotm += Es[ti][c1] * Ms[c1][c];
        float s = g_C[((size_t)k * NN + i) * DD + c] + alpha * dotm;
        acc += g_dinv[(size_t)k * NN + i] * s;
    }
    out[(size_t)i * DD + c] = fmaxf(acc, 0.f);
}

// ---------------- launch ----------------------------------------------------
extern "C" void kernel_launch(void* const* d_in, const int* in_sizes, int n_in,
                              void* d_out, int out_size) {
    const float* X     = (const float*)d_in[0];
    const float* A     = (const float*)d_in[1];
    const float* Wemb  = (const float*)d_in[2];
    const float* Whops = (const float*)d_in[3];
    const float* alpha = (const float*)d_in[4];
    float* out = (float*)d_out;

    zero_kernel<<<48, 256>>>();
    proj_kernel<<<dim3(256, 4), 256>>>(X, Wemb, Whops);
    colsum_kernel<<<32, 256>>>();
    deg_kernel<<<KH * NN, 256>>>(A, alpha);
    mmat_kernel<<<dim3(64, KH), 256>>>();
    spmm_kernel<<<dim3(128, KH), 128>>>(A);
    final_kernel<<<1024, 256>>>(alpha, out);
}

// round 8
// speedup vs baseline: 3.4946x; 3.4946x over previous
#include <cuda_runtime.h>
#include <math.h>
#include <cstdint>

#define NN 4096
#define FF 128
#define DD 64
#define KH 3
#define SPLIT 4
#define KSPLIT (NN / SPLIT)     // 1024
#define KCHUNK 32
#define NCH (KSPLIT / KCHUNK)   // 32

// ---------------- scratch (device globals; no allocations allowed) ----------
__device__ float g_E[NN * DD];                 // X @ W_emb
__device__ float g_XW[KH * NN * DD];           // per-hop projections
__device__ float g_Yt[KH * DD * NN];           // (d .* XW)^T  [k][n][j]
__device__ float g_Cp[SPLIT * KH * NN * DD];   // partial C per K-split
__device__ float g_dinv[KH * NN];              // deg^{-1/2}
__device__ float g_S[DD];                      // colsum(E)
__device__ float g_M[KH * DD * DD];            // M_k = E^T @ Y_k

// ---------------- helpers ----------------------------------------------------
__device__ __forceinline__ uint32_t smem_u32(const void* p) {
    uint32_t a;
    asm("{ .reg .u64 t; cvta.to.shared.u64 t, %1; cvt.u32.u64 %0, t; }" : "=r"(a) : "l"(p));
    return a;
}
#define CP_ASYNC16(dst, src) \
    asm volatile("cp.async.cg.shared.global [%0], [%1], 16;" :: "r"(dst), "l"(src) : "memory")
#define CP_COMMIT() asm volatile("cp.async.commit_group;" ::: "memory")
#define CP_WAIT(n)  asm volatile("cp.async.wait_group %0;" :: "n"(n) : "memory")

__device__ __forceinline__ void mma_tf32(float& d0, float& d1, float& d2, float& d3,
                                         uint32_t a0, uint32_t a1, uint32_t a2, uint32_t a3,
                                         uint32_t b0, uint32_t b1) {
    asm volatile(
        "mma.sync.aligned.m16n8k8.row.col.f32.tf32.tf32.f32 "
        "{%0,%1,%2,%3}, {%4,%5,%6,%7}, {%8,%9}, {%0,%1,%2,%3};\n"
        : "+f"(d0), "+f"(d1), "+f"(d2), "+f"(d3)
        : "r"(a0), "r"(a1), "r"(a2), "r"(a3), "r"(b0), "r"(b1));
}

__device__ __forceinline__ uint32_t hi_bits(float a) {
    return __float_as_uint(a) & 0xFFFFE000u;
}
__device__ __forceinline__ uint32_t lo_bits(float a, uint32_t h) {
    return __float_as_uint(a - __uint_as_float(h));
}

// ---------------- zero the atomic accumulators ------------------------------
__global__ void zero_kernel() {
    int t = blockIdx.x * blockDim.x + threadIdx.x;
    if (t < DD) g_S[t] = 0.f;
    if (t < KH * DD * DD) g_M[t] = 0.f;
}

// ---------------- E = X @ W_emb, XW[k] = X @ W_hops[k] ----------------------
__global__ void proj_kernel(const float* __restrict__ X,
                            const float* __restrict__ Wemb,
                            const float* __restrict__ Whops) {
    __shared__ float Xs[16][FF + 1];
    const int rb = blockIdx.x;
    const int m = blockIdx.y;
    const float* W = (m == 0) ? Wemb : (Whops + (size_t)(m - 1) * FF * DD);
    float* Out = (m == 0) ? g_E : (g_XW + (size_t)(m - 1) * NN * DD);
    const int t = threadIdx.x;

    #pragma unroll
    for (int i = 0; i < 2; i++) {
        int idx = t + 256 * i;
        int row = idx >> 5;
        int c4 = idx & 31;
        float4 v = *reinterpret_cast<const float4*>(X + (size_t)(rb * 16 + row) * FF + c4 * 4);
        Xs[row][c4 * 4 + 0] = v.x; Xs[row][c4 * 4 + 1] = v.y;
        Xs[row][c4 * 4 + 2] = v.z; Xs[row][c4 * 4 + 3] = v.w;
    }
    __syncthreads();

    const int c = t & 63;
    const int rq = t >> 6;
    float acc[4] = {0.f, 0.f, 0.f, 0.f};
    for (int f = 0; f < FF; f++) {
        float w = __ldg(W + (size_t)f * DD + c);
        #pragma unroll
        for (int r = 0; r < 4; r++) acc[r] += Xs[rq * 4 + r][f] * w;
    }
    #pragma unroll
    for (int r = 0; r < 4; r++)
        Out[(size_t)(rb * 16 + rq * 4 + r) * DD + c] = acc[r];
}

// ---------------- S = colsum(E). grid 32, block 256 -------------------------
__global__ void colsum_kernel() {
    __shared__ float red[4][DD];
    const int t = threadIdx.x;
    const int b = blockIdx.x;
    const int c = t & 63, g = t >> 6;
    float acc = 0.f;
    for (int r = 0; r < 32; r++)
        acc += g_E[(size_t)(b * 128 + g * 32 + r) * DD + c];
    red[g][c] = acc;
    __syncthreads();
    if (t < DD)
        atomicAdd(&g_S[t], red[0][t] + red[1][t] + red[2][t] + red[3][t]);
}

// ---------------- dinv[k][i] = (rowsum(A_k)[i] + alpha*E[i].S)^(-1/2) -------
__global__ void deg_kernel(const float* __restrict__ A,
                           const float* __restrict__ alpha_p) {
    __shared__ float wsum[8];
    __shared__ float dsum[2];
    const int bid = blockIdx.x;           // k*NN + i
    const int i = bid & (NN - 1);
    const float* Arow = A + (size_t)bid * NN;
    const int t = threadIdx.x;

    float acc = 0.f;
    #pragma unroll
    for (int j = 0; j < 4; j++) {
        float4 v = *reinterpret_cast<const float4*>(Arow + (size_t)(t + 256 * j) * 4);
        acc += (v.x + v.y) + (v.z + v.w);
    }
    #pragma unroll
    for (int o = 16; o > 0; o >>= 1) acc += __shfl_down_sync(0xffffffffu, acc, o);
    if ((t & 31) == 0) wsum[t >> 5] = acc;
    __syncthreads();
    if (t < 64) {
        float p = g_E[(size_t)i * DD + t] * g_S[t];
        #pragma unroll
        for (int o = 16; o > 0; o >>= 1) p += __shfl_down_sync(0xffffffffu, p, o);
        if ((t & 31) == 0) dsum[t >> 5] = p;
    }
    __syncthreads();
    if (t == 0) {
        float rs = 0.f;
        #pragma unroll
        for (int w = 0; w < 8; w++) rs += wsum[w];
        float deg = rs + __ldg(alpha_p) * (dsum[0] + dsum[1]);
        g_dinv[bid] = 1.0f / sqrtf(deg);
    }
}

// ---------------- Yt[k][n][j] = dinv[k][j] * XW[k][j][n]  (transpose) -------
// grid (64, KH), block 256 — 64x64 transpose tiles.
__global__ void prep_kernel() {
    __shared__ float T[64][65];
    const int k = blockIdx.y;
    const int jb = blockIdx.x * 64;
    const int t = threadIdx.x;

    #pragma unroll
    for (int q = 0; q < 4; q++) {
        int idx = t + 256 * q;            // 1024 float4
        int r = idx >> 4;
        int c4 = idx & 15;
        float dv = g_dinv[(size_t)k * NN + jb + r];
        float4 v = *reinterpret_cast<const float4*>(g_XW + ((size_t)k * NN + jb + r) * DD + c4 * 4);
        T[r][c4 * 4 + 0] = v.x * dv;
        T[r][c4 * 4 + 1] = v.y * dv;
        T[r][c4 * 4 + 2] = v.z * dv;
        T[r][c4 * 4 + 3] = v.w * dv;
    }
    __syncthreads();

    const int n = t >> 2;
    const int jq = t & 3;
    float* o = g_Yt + ((size_t)k * DD + n) * NN + jb + jq * 16;
    #pragma unroll
    for (int m4 = 0; m4 < 4; m4++) {
        float4 y = make_float4(T[jq * 16 + m4 * 4 + 0][n],
                               T[jq * 16 + m4 * 4 + 1][n],
                               T[jq * 16 + m4 * 4 + 2][n],
                               T[jq * 16 + m4 * 4 + 3][n]);
        *reinterpret_cast<float4*>(o + m4 * 4) = y;
    }
}

// ---------------- M_k = E^T @ (d_k . XW_k)  (64x64 each) --------------------
__global__ void mmat_kernel() {
    __shared__ float Es[64][DD];
    __shared__ float Ys[64][DD];
    const int k = blockIdx.y;
    const int base = blockIdx.x * 64;
    const int t = threadIdx.x;

    #pragma unroll
    for (int i = 0; i < 4; i++) {
        int idx = t + 256 * i;
        int row = idx >> 4;
        int c4 = idx & 15;
        float4 e = *reinterpret_cast<const float4*>(g_E + (size_t)(base + row) * DD + c4 * 4);
        *reinterpret_cast<float4*>(&Es[row][c4 * 4]) = e;
        float dv = g_dinv[(size_t)k * NN + base + row];
        float4 xw = *reinterpret_cast<const float4*>(g_XW + ((size_t)k * NN + base + row) * DD + c4 * 4);
        xw.x *= dv; xw.y *= dv; xw.z *= dv; xw.w *= dv;
        *reinterpret_cast<float4*>(&Ys[row][c4 * 4]) = xw;
    }
    __syncthreads();

    const int t1 = t >> 4, t2 = t & 15;
    float acc[4][4] = {};
    for (int j = 0; j < 64; j++) {
        float4 e = *reinterpret_cast<const float4*>(&Es[j][t1 * 4]);
        float4 y = *reinterpret_cast<const float4*>(&Ys[j][t2 * 4]);
        float ea[4] = {e.x, e.y, e.z, e.w};
        float ya[4] = {y.x, y.y, y.z, y.w};
        #pragma unroll
        for (int a = 0; a < 4; a++)
            #pragma unroll
            for (int b = 0; b < 4; b++) acc[a][b] += ea[a] * ya[b];
    }
    #pragma unroll
    for (int a = 0; a < 4; a++)
        #pragma unroll
        for (int b = 0; b < 4; b++)
            atomicAdd(&g_M[(size_t)k * DD * DD + (t1 * 4 + a) * DD + t2 * 4 + b], acc[a][b]);
}

// ---------------- C_k = A_k @ Y_k via mma.sync tf32 (3-MMA exact split) -----
// grid (32, KH, SPLIT), block 256 (8 warps, warp tile 32x32).
// CTA tile 128(M) x 64(N), K chunk 32, cp.async double buffer.
// Smem layout rotation: element (row,k) at column (k + 4*(row&7)) & 31
// -> fragment LDS is conflict-free.
#define STAGE_FLOATS (128 * 32 + 64 * 32)   // 6144
#define SPMM_SMEM (2 * STAGE_FLOATS * 4)    // 49152 bytes

__global__ void __launch_bounds__(256, 1) spmm_mma_kernel(const float* __restrict__ A) {
    extern __shared__ float smem[];
    const uint32_t sb = smem_u32(smem);
    const int t = threadIdx.x;
    const int wid = t >> 5;
    const int lid = t & 31;
    const int g = lid >> 2;                // 0..7
    const int tig = lid & 3;               // 0..3
    const int warpM = wid >> 1;            // 0..3
    const int warpN = wid & 1;             // 0..1
    const int k = blockIdx.y;
    const int r0 = blockIdx.x * 128;
    const int kz = blockIdx.z;
    const size_t k0 = (size_t)kz * KSPLIT;

    // ---- fill geometry ----
    // A: 4 x 16B per thread per chunk
    int arow[4], adst[4];
    const float* asrc[4];
    #pragma unroll
    for (int q = 0; q < 4; q++) {
        int idx = t + 256 * q;
        int row = idx >> 3;                // 0..127
        int c4 = idx & 7;
        arow[q] = row;
        adst[q] = row * 32 + ((c4 * 4 + 4 * (row & 7)) & 31);
        asrc[q] = A + ((size_t)k * NN + r0 + row) * NN + k0 + c4 * 4;
    }
    // B: 2 x 16B per thread per chunk
    int bdst[2];
    const float* bsrc[2];
    #pragma unroll
    for (int q = 0; q < 2; q++) {
        int idx = t + 256 * q;
        int row = idx >> 3;                // 0..63
        int c4 = idx & 7;
        bdst[q] = 4096 + row * 32 + ((c4 * 4 + 4 * (row & 7)) & 31);
        bsrc[q] = g_Yt + ((size_t)k * DD + row) * NN + k0 + c4 * 4;
    }

    float acc[2][4][4];
    #pragma unroll
    for (int mt = 0; mt < 2; mt++)
        #pragma unroll
        for (int nt = 0; nt < 4; nt++)
            #pragma unroll
            for (int r = 0; r < 4; r++) acc[mt][nt][r] = 0.f;

    // issue chunk 0
    {
        #pragma unroll
        for (int q = 0; q < 4; q++) CP_ASYNC16(sb + adst[q] * 4, asrc[q]);
        #pragma unroll
        for (int q = 0; q < 2; q++) CP_ASYNC16(sb + bdst[q] * 4, bsrc[q]);
        CP_COMMIT();
    }

    for (int i = 0; i < NCH; i++) {
        const int st = i & 1;
        if (i + 1 < NCH) {
            const uint32_t soff = sb + ((i + 1) & 1) * (STAGE_FLOATS * 4);
            const int kb = (i + 1) * KCHUNK;
            #pragma unroll
            for (int q = 0; q < 4; q++) CP_ASYNC16(soff + adst[q] * 4, asrc[q] + kb);
            #pragma unroll
            for (int q = 0; q < 2; q++) CP_ASYNC16(soff + bdst[q] * 4, bsrc[q] + kb);
            CP_COMMIT();
            CP_WAIT(1);
        } else {
            CP_WAIT(0);
        }
        __syncthreads();

        const float* sA = smem + st * STAGE_FLOATS;
        const float* sB = sA + 4096;

        #pragma unroll
        for (int kb8 = 0; kb8 < 4; kb8++) {
            const int col0 = (kb8 * 8 + tig + 4 * g) & 31;
            const int col4 = (col0 + 4) & 31;

            uint32_t ah[2][4], al[2][4];
            #pragma unroll
            for (int mt = 0; mt < 2; mt++) {
                const int bm = warpM * 32 + mt * 16;
                float a0 = sA[(bm + g) * 32 + col0];
                float a1 = sA[(bm + 8 + g) * 32 + col0];
                float a2 = sA[(bm + g) * 32 + col4];
                float a3 = sA[(bm + 8 + g) * 32 + col4];
                ah[mt][0] = hi_bits(a0); al[mt][0] = lo_bits(a0, ah[mt][0]);
                ah[mt][1] = hi_bits(a1); al[mt][1] = lo_bits(a1, ah[mt][1]);
                ah[mt][2] = hi_bits(a2); al[mt][2] = lo_bits(a2, ah[mt][2]);
                ah[mt][3] = hi_bits(a3); al[mt][3] = lo_bits(a3, ah[mt][3]);
            }
            uint32_t bh[4][2], bl[4][2];
            #pragma unroll
            for (int nt = 0; nt < 4; nt++) {
                const int bn = warpN * 32 + nt * 8;
                float b0 = sB[(bn + g) * 32 + col0];
                float b1 = sB[(bn + g) * 32 + col4];
                bh[nt][0] = hi_bits(b0); bl[nt][0] = lo_bits(b0, bh[nt][0]);
                bh[nt][1] = hi_bits(b1); bl[nt][1] = lo_bits(b1, bh[nt][1]);
            }
            #pragma unroll
            for (int mt = 0; mt < 2; mt++)
                #pragma unroll
                for (int nt = 0; nt < 4; nt++) {
                    float* d = acc[mt][nt];
                    mma_tf32(d[0], d[1], d[2], d[3],
                             ah[mt][0], ah[mt][1], ah[mt][2], ah[mt][3],
                             bh[nt][0], bh[nt][1]);
                    mma_tf32(d[0], d[1], d[2], d[3],
                             ah[mt][0], ah[mt][1], ah[mt][2], ah[mt][3],
                             bl[nt][0], bl[nt][1]);
                    mma_tf32(d[0], d[1], d[2], d[3],
                             al[mt][0], al[mt][1], al[mt][2], al[mt][3],
                             bh[nt][0], bh[nt][1]);
                }
        }
        __syncthreads();
    }

    // ---- epilogue: write partial C ----
    float* Cb = g_Cp + ((size_t)kz * KH + k) * NN * DD + (size_t)r0 * DD;
    #pragma unroll
    for (int mt = 0; mt < 2; mt++) {
        const int row = warpM * 32 + mt * 16 + g;
        #pragma unroll
        for (int nt = 0; nt < 4; nt++) {
            const int col = warpN * 32 + nt * 8 + 2 * tig;
            *reinterpret_cast<float2*>(Cb + (size_t)row * DD + col) =
                make_float2(acc[mt][nt][0], acc[mt][nt][1]);
            *reinterpret_cast<float2*>(Cb + (size_t)(row + 8) * DD + col) =
                make_float2(acc[mt][nt][2], acc[mt][nt][3]);
        }
    }
}

// ---------------- out = relu( sum_k dinv_k[i] * (sum_z Cp + alpha*E@M_k) ) --
__global__ void final_kernel(const float* __restrict__ alpha_p,
                             float* __restrict__ out) {
    __shared__ float Ms[DD][DD];
    __shared__ float Es[4][DD];
    const int b = blockIdx.x;
    const int t = threadIdx.x;
    const int ti = t >> 6, c = t & 63;
    const int i = b * 4 + ti;
    Es[ti][c] = g_E[(size_t)i * DD + c];
    const float alpha = __ldg(alpha_p);

    float acc = 0.f;
    for (int k = 0; k < KH; k++) {
        __syncthreads();
        #pragma unroll
        for (int q = 0; q < 16; q++) {
            int idx = t + 256 * q;
            Ms[idx >> 6][idx & 63] = g_M[(size_t)k * DD * DD + idx];
        }
        __syncthreads();
        float dotm = 0.f;
        #pragma unroll 8
        for (int c1 = 0; c1 < DD; c1++) dotm += Es[ti][c1] * Ms[c1][c];
        size_t idx = ((size_t)k * NN + i) * DD + c;
        float s = alpha * dotm;
        #pragma unroll
        for (int z = 0; z < SPLIT; z++)
            s += g_Cp[(size_t)z * (KH * NN * DD) + idx];
        acc += g_dinv[(size_t)k * NN + i] * s;
    }
    out[(size_t)i * DD + c] = fmaxf(acc, 0.f);
}

// ---------------- launch ----------------------------------------------------
extern "C" void kernel_launch(void* const* d_in, const int* in_sizes, int n_in,
                              void* d_out, int out_size) {
    const float* X     = (const float*)d_in[0];
    const float* A     = (const float*)d_in[1];
    const float* Wemb  = (const float*)d_in[2];
    const float* Whops = (const float*)d_in[3];
    const float* alpha = (const float*)d_in[4];
    float* out = (float*)d_out;

    cudaFuncSetAttribute(spmm_mma_kernel,
                         cudaFuncAttributeMaxDynamicSharedMemorySize, SPMM_SMEM);

    zero_kernel<<<48, 256>>>();
    proj_kernel<<<dim3(256, 4), 256>>>(X, Wemb, Whops);
    colsum_kernel<<<32, 256>>>();
    deg_kernel<<<KH * NN, 256>>>(A, alpha);
    prep_kernel<<<dim3(64, KH), 256>>>();
    mmat_kernel<<<dim3(64, KH), 256>>>();
    spmm_mma_kernel<<<dim3(32, KH, SPLIT), 256, SPMM_SMEM>>>(A);
    final_kernel<<<1024, 256>>>(alpha, out);
}

// round 9
// speedup vs baseline: 4.2743x; 1.2231x over previous
#include <cuda_runtime.h>
#include <cuda_bf16.h>
#include <math.h>
#include <cstdint>

#define NN 4096
#define FF 128
#define DD 64
#define KH 3
#define SPLIT 4
#define KSPLIT (NN / SPLIT)     // 1024
#define KCHUNK 32
#define NCH (KSPLIT / KCHUNK)   // 32

// ---------------- scratch (device globals; no allocations allowed) ----------
__device__ float g_E[NN * DD];                 // X @ W_emb
__device__ float g_XW[KH * NN * DD];           // per-hop projections
__device__ __align__(16) __nv_bfloat16 g_Ybh[KH * DD * NN]; // (d.*XW)^T hi bf16
__device__ __align__(16) __nv_bfloat16 g_Ybl[KH * DD * NN]; // (d.*XW)^T lo bf16
__device__ float g_Cp[SPLIT * KH * NN * DD];   // partial C per K-split
__device__ float g_dinv[KH * NN];              // deg^{-1/2}
__device__ float g_S[DD];                      // colsum(E)
__device__ float g_M[KH * DD * DD];            // M_k = E^T @ Y_k

// ---------------- helpers ----------------------------------------------------
__device__ __forceinline__ uint32_t smem_u32(const void* p) {
    uint32_t a;
    asm("{ .reg .u64 t; cvta.to.shared.u64 t, %1; cvt.u32.u64 %0, t; }" : "=r"(a) : "l"(p));
    return a;
}
#define CP_ASYNC16(dst, src) \
    asm volatile("cp.async.cg.shared.global [%0], [%1], 16;" :: "r"(dst), "l"(src) : "memory")
#define CP_COMMIT() asm volatile("cp.async.commit_group;" ::: "memory")
#define CP_WAIT(n)  asm volatile("cp.async.wait_group %0;" :: "n"(n) : "memory")

// exact 2-term bf16 split of a float pair (x = low/even-k, y = high/odd-k)
__device__ __forceinline__ void split_bf16x2(float x, float y, uint32_t& h, uint32_t& l) {
    asm("cvt.rn.bf16x2.f32 %0, %1, %2;" : "=r"(h) : "f"(y), "f"(x));
    float hx = __uint_as_float(h << 16);
    float hy = __uint_as_float(h & 0xFFFF0000u);
    float lx = x - hx;
    float ly = y - hy;
    asm("cvt.rn.bf16x2.f32 %0, %1, %2;" : "=r"(l) : "f"(ly), "f"(lx));
}

__device__ __forceinline__ void mma_bf16(float* d, const uint32_t* a, const uint32_t* b) {
    asm volatile(
        "mma.sync.aligned.m16n8k16.row.col.f32.bf16.bf16.f32 "
        "{%0,%1,%2,%3}, {%4,%5,%6,%7}, {%8,%9}, {%0,%1,%2,%3};\n"
        : "+f"(d[0]), "+f"(d[1]), "+f"(d[2]), "+f"(d[3])
        : "r"(a[0]), "r"(a[1]), "r"(a[2]), "r"(a[3]), "r"(b[0]), "r"(b[1]));
}

// ---------------- zero the atomic accumulators ------------------------------
__global__ void zero_kernel() {
    int t = blockIdx.x * blockDim.x + threadIdx.x;
    if (t < DD) g_S[t] = 0.f;
    if (t < KH * DD * DD) g_M[t] = 0.f;
}

// ---------------- E = X @ W_emb, XW[k] = X @ W_hops[k] ----------------------
__global__ void proj_kernel(const float* __restrict__ X,
                            const float* __restrict__ Wemb,
                            const float* __restrict__ Whops) {
    __shared__ float Xs[16][FF + 1];
    const int rb = blockIdx.x;
    const int m = blockIdx.y;
    const float* W = (m == 0) ? Wemb : (Whops + (size_t)(m - 1) * FF * DD);
    float* Out = (m == 0) ? g_E : (g_XW + (size_t)(m - 1) * NN * DD);
    const int t = threadIdx.x;

    #pragma unroll
    for (int i = 0; i < 2; i++) {
        int idx = t + 256 * i;
        int row = idx >> 5;
        int c4 = idx & 31;
        float4 v = *reinterpret_cast<const float4*>(X + (size_t)(rb * 16 + row) * FF + c4 * 4);
        Xs[row][c4 * 4 + 0] = v.x; Xs[row][c4 * 4 + 1] = v.y;
        Xs[row][c4 * 4 + 2] = v.z; Xs[row][c4 * 4 + 3] = v.w;
    }
    __syncthreads();

    const int c = t & 63;
    const int rq = t >> 6;
    float acc[4] = {0.f, 0.f, 0.f, 0.f};
    for (int f = 0; f < FF; f++) {
        float w = __ldg(W + (size_t)f * DD + c);
        #pragma unroll
        for (int r = 0; r < 4; r++) acc[r] += Xs[rq * 4 + r][f] * w;
    }
    #pragma unroll
    for (int r = 0; r < 4; r++)
        Out[(size_t)(rb * 16 + rq * 4 + r) * DD + c] = acc[r];
}

// ---------------- S = colsum(E). grid 32, block 256 -------------------------
__global__ void colsum_kernel() {
    __shared__ float red[4][DD];
    const int t = threadIdx.x;
    const int b = blockIdx.x;
    const int c = t & 63, g = t >> 6;
    float acc = 0.f;
    for (int r = 0; r < 32; r++)
        acc += g_E[(size_t)(b * 128 + g * 32 + r) * DD + c];
    red[g][c] = acc;
    __syncthreads();
    if (t < DD)
        atomicAdd(&g_S[t], red[0][t] + red[1][t] + red[2][t] + red[3][t]);
}

// ---------------- dinv[k][i] = (rowsum(A_k)[i] + alpha*E[i].S)^(-1/2) -------
__global__ void deg_kernel(const float* __restrict__ A,
                           const float* __restrict__ alpha_p) {
    __shared__ float wsum[8];
    __shared__ float dsum[2];
    const int bid = blockIdx.x;           // k*NN + i
    const int i = bid & (NN - 1);
    const float* Arow = A + (size_t)bid * NN;
    const int t = threadIdx.x;

    float acc = 0.f;
    #pragma unroll
    for (int j = 0; j < 4; j++) {
        float4 v = *reinterpret_cast<const float4*>(Arow + (size_t)(t + 256 * j) * 4);
        acc += (v.x + v.y) + (v.z + v.w);
    }
    #pragma unroll
    for (int o = 16; o > 0; o >>= 1) acc += __shfl_down_sync(0xffffffffu, acc, o);
    if ((t & 31) == 0) wsum[t >> 5] = acc;
    __syncthreads();
    if (t < 64) {
        float p = g_E[(size_t)i * DD + t] * g_S[t];
        #pragma unroll
        for (int o = 16; o > 0; o >>= 1) p += __shfl_down_sync(0xffffffffu, p, o);
        if ((t & 31) == 0) dsum[t >> 5] = p;
    }
    __syncthreads();
    if (t == 0) {
        float rs = 0.f;
        #pragma unroll
        for (int w = 0; w < 8; w++) rs += wsum[w];
        float deg = rs + __ldg(alpha_p) * (dsum[0] + dsum[1]);
        g_dinv[bid] = 1.0f / sqrtf(deg);
    }
}

// ---------------- Ybh/Ybl[k][n][j] = split_bf16( dinv[k][j] * XW[k][j][n] ) -
// grid (64, KH), block 256 — 64x64 transpose tiles.
__global__ void prep_kernel() {
    __shared__ float T[64][65];
    const int k = blockIdx.y;
    const int jb = blockIdx.x * 64;
    const int t = threadIdx.x;

    #pragma unroll
    for (int q = 0; q < 4; q++) {
        int idx = t + 256 * q;            // 1024 float4
        int r = idx >> 4;
        int c4 = idx & 15;
        float dv = g_dinv[(size_t)k * NN + jb + r];
        float4 v = *reinterpret_cast<const float4*>(g_XW + ((size_t)k * NN + jb + r) * DD + c4 * 4);
        T[r][c4 * 4 + 0] = v.x * dv;
        T[r][c4 * 4 + 1] = v.y * dv;
        T[r][c4 * 4 + 2] = v.z * dv;
        T[r][c4 * 4 + 3] = v.w * dv;
    }
    __syncthreads();

    const int n = t >> 2;
    const int jq = t & 3;
    const size_t base = ((size_t)k * DD + n) * NN + jb + jq * 16;
    #pragma unroll
    for (int m4 = 0; m4 < 4; m4++) {
        float y0 = T[jq * 16 + m4 * 4 + 0][n];
        float y1 = T[jq * 16 + m4 * 4 + 1][n];
        float y2 = T[jq * 16 + m4 * 4 + 2][n];
        float y3 = T[jq * 16 + m4 * 4 + 3][n];
        uint32_t h01, l01, h23, l23;
        split_bf16x2(y0, y1, h01, l01);
        split_bf16x2(y2, y3, h23, l23);
        *reinterpret_cast<uint2*>(g_Ybh + base + m4 * 4) = make_uint2(h01, h23);
        *reinterpret_cast<uint2*>(g_Ybl + base + m4 * 4) = make_uint2(l01, l23);
    }
}

// ---------------- M_k = E^T @ (d_k . XW_k)  (64x64 each) --------------------
__global__ void mmat_kernel() {
    __shared__ float Es[64][DD];
    __shared__ float Ys[64][DD];
    const int k = blockIdx.y;
    const int base = blockIdx.x * 64;
    const int t = threadIdx.x;

    #pragma unroll
    for (int i = 0; i < 4; i++) {
        int idx = t + 256 * i;
        int row = idx >> 4;
        int c4 = idx & 15;
        float4 e = *reinterpret_cast<const float4*>(g_E + (size_t)(base + row) * DD + c4 * 4);
        *reinterpret_cast<float4*>(&Es[row][c4 * 4]) = e;
        float dv = g_dinv[(size_t)k * NN + base + row];
        float4 xw = *reinterpret_cast<const float4*>(g_XW + ((size_t)k * NN + base + row) * DD + c4 * 4);
        xw.x *= dv; xw.y *= dv; xw.z *= dv; xw.w *= dv;
        *reinterpret_cast<float4*>(&Ys[row][c4 * 4]) = xw;
    }
    __syncthreads();

    const int t1 = t >> 4, t2 = t & 15;
    float acc[4][4] = {};
    for (int j = 0; j < 64; j++) {
        float4 e = *reinterpret_cast<const float4*>(&Es[j][t1 * 4]);
        float4 y = *reinterpret_cast<const float4*>(&Ys[j][t2 * 4]);
        float ea[4] = {e.x, e.y, e.z, e.w};
        float ya[4] = {y.x, y.y, y.z, y.w};
        #pragma unroll
        for (int a = 0; a < 4; a++)
            #pragma unroll
            for (int b = 0; b < 4; b++) acc[a][b] += ea[a] * ya[b];
    }
    #pragma unroll
    for (int a = 0; a < 4; a++)
        #pragma unroll
        for (int b = 0; b < 4; b++)
            atomicAdd(&g_M[(size_t)k * DD * DD + (t1 * 4 + a) * DD + t2 * 4 + b], acc[a][b]);
}

// ---------------- C_k = A_k @ Y_k via mma.sync bf16 m16n8k16 (3-MMA split) --
// grid (32, KH, SPLIT), block 256 (8 warps, warp tile 32x32).
// A staged f32 (split to bf16 hi/lo in registers); B staged pre-split bf16.
// A smem: [128][32] f32, pair-rotation: pair p at p' = (p + 4*(row&3)) & 15.
// B smem: [64][32] bf16 (hi then lo), pair p' = (p + 4*((row>>1)&3)) & 15.
#define A_STAGE 16384                         // 128*32*4
#define B_STAGE 4096                          // 64*32*2
#define STAGE_BYTES (A_STAGE + 2 * B_STAGE)   // 24576
#define SPMM_SMEM (2 * STAGE_BYTES)           // 49152

__global__ void __launch_bounds__(256, 2) spmm_mma_kernel(const float* __restrict__ A) {
    extern __shared__ char smem[];
    const uint32_t sb = smem_u32(smem);
    const int t = threadIdx.x;
    const int wid = t >> 5;
    const int lid = t & 31;
    const int g = lid >> 2;                // 0..7
    const int tig = lid & 3;               // 0..3
    const int warpM = wid >> 1;            // 0..3
    const int warpN = wid & 1;             // 0..1
    const int k = blockIdx.y;
    const int r0 = blockIdx.x * 128;
    const int kz = blockIdx.z;
    const size_t k0 = (size_t)kz * KSPLIT;

    // ---- fill geometry ----
    uint32_t adst[4];
    const float* asrc[4];
    #pragma unroll
    for (int q = 0; q < 4; q++) {
        int idx = t + 256 * q;
        int row = idx >> 3;                // 0..127
        int c4 = idx & 7;                  // 16B unit -> pairs 2c4, 2c4+1
        adst[q] = (uint32_t)(row * 128 + 8 * ((2 * c4 + 4 * (row & 3)) & 15));
        asrc[q] = A + ((size_t)k * NN + r0 + row) * NN + k0 + c4 * 4;
    }
    uint32_t bdst;
    const __nv_bfloat16 *bsh, *bsl;
    {
        int row = t >> 2;                  // 0..63
        int c8 = t & 3;                    // 16B unit -> pairs 4c8..4c8+3
        bdst = (uint32_t)(row * 64 + 16 * ((c8 + ((row >> 1) & 3)) & 3));
        bsh = g_Ybh + ((size_t)k * DD + row) * NN + k0 + c8 * 8;
        bsl = g_Ybl + ((size_t)k * DD + row) * NN + k0 + c8 * 8;
    }

    float acc[2][4][4];
    #pragma unroll
    for (int mt = 0; mt < 2; mt++)
        #pragma unroll
        for (int nt = 0; nt < 4; nt++)
            #pragma unroll
            for (int r = 0; r < 4; r++) acc[mt][nt][r] = 0.f;

    // issue chunk 0
    {
        #pragma unroll
        for (int q = 0; q < 4; q++) CP_ASYNC16(sb + adst[q], asrc[q]);
        CP_ASYNC16(sb + A_STAGE + bdst, bsh);
        CP_ASYNC16(sb + A_STAGE + B_STAGE + bdst, bsl);
        CP_COMMIT();
    }

    for (int i = 0; i < NCH; i++) {
        const int st = i & 1;
        if (i + 1 < NCH) {
            const uint32_t soff = sb + ((i + 1) & 1) * STAGE_BYTES;
            const int kb = (i + 1) * KCHUNK;
            #pragma unroll
            for (int q = 0; q < 4; q++) CP_ASYNC16(soff + adst[q], asrc[q] + kb);
            CP_ASYNC16(soff + A_STAGE + bdst, bsh + kb);
            CP_ASYNC16(soff + A_STAGE + B_STAGE + bdst, bsl + kb);
            CP_COMMIT();
            CP_WAIT(1);
        } else {
            CP_WAIT(0);
        }
        __syncthreads();

        const float* sA = reinterpret_cast<const float*>(smem + st * STAGE_BYTES);
        const uint32_t* sBh = reinterpret_cast<const uint32_t*>(smem + st * STAGE_BYTES + A_STAGE);
        const uint32_t* sBl = sBh + (B_STAGE / 4);

        #pragma unroll
        for (int kb16 = 0; kb16 < 2; kb16++) {
            const int p0 = kb16 * 8;

            // A fragments: LDS.64 + in-register bf16 split
            uint32_t ah[2][4], al[2][4];
            const int rotA = 4 * (g & 3);
            const int cA0 = 2 * ((p0 + tig + rotA) & 15);
            const int cA2 = 2 * ((p0 + tig + 4 + rotA) & 15);
            #pragma unroll
            for (int mt = 0; mt < 2; mt++) {
                const int ra = warpM * 32 + mt * 16 + g;
                const int rb = ra + 8;
                float2 x0 = *reinterpret_cast<const float2*>(sA + ra * 32 + cA0);
                float2 x1 = *reinterpret_cast<const float2*>(sA + rb * 32 + cA0);
                float2 x2 = *reinterpret_cast<const float2*>(sA + ra * 32 + cA2);
                float2 x3 = *reinterpret_cast<const float2*>(sA + rb * 32 + cA2);
                split_bf16x2(x0.x, x0.y, ah[mt][0], al[mt][0]);
                split_bf16x2(x1.x, x1.y, ah[mt][1], al[mt][1]);
                split_bf16x2(x2.x, x2.y, ah[mt][2], al[mt][2]);
                split_bf16x2(x3.x, x3.y, ah[mt][3], al[mt][3]);
            }

            // B fragments: direct bf16x2 LDS.32
            uint32_t bh[4][2], bl[4][2];
            const int rotB = 4 * ((g >> 1) & 3);
            const int pB0 = (p0 + tig + rotB) & 15;
            const int pB1 = (p0 + tig + 4 + rotB) & 15;
            #pragma unroll
            for (int nt = 0; nt < 4; nt++) {
                const int rn_ = warpN * 32 + nt * 8 + g;
                bh[nt][0] = sBh[rn_ * 16 + pB0];
                bh[nt][1] = sBh[rn_ * 16 + pB1];
                bl[nt][0] = sBl[rn_ * 16 + pB0];
                bl[nt][1] = sBl[rn_ * 16 + pB1];
            }

            #pragma unroll
            for (int mt = 0; mt < 2; mt++)
                #pragma unroll
                for (int nt = 0; nt < 4; nt++) {
                    mma_bf16(acc[mt][nt], ah[mt], bh[nt]);
                    mma_bf16(acc[mt][nt], ah[mt], bl[nt]);
                    mma_bf16(acc[mt][nt], al[mt], bh[nt]);
                }
        }
        __syncthreads();
    }

    // ---- epilogue: write partial C ----
    float* Cb = g_Cp + ((size_t)kz * KH + k) * NN * DD + (size_t)r0 * DD;
    #pragma unroll
    for (int mt = 0; mt < 2; mt++) {
        const int row = warpM * 32 + mt * 16 + g;
        #pragma unroll
        for (int nt = 0; nt < 4; nt++) {
            const int col = warpN * 32 + nt * 8 + 2 * tig;
            *reinterpret_cast<float2*>(Cb + (size_t)row * DD + col) =
                make_float2(acc[mt][nt][0], acc[mt][nt][1]);
            *reinterpret_cast<float2*>(Cb + (size_t)(row + 8) * DD + col) =
                make_float2(acc[mt][nt][2], acc[mt][nt][3]);
        }
    }
}

// ---------------- out = relu( sum_k dinv_k[i] * (sum_z Cp + alpha*E@M_k) ) --
__global__ void final_kernel(const float* __restrict__ alpha_p,
                             float* __restrict__ out) {
    __shared__ float Ms[DD][DD];
    __shared__ float Es[4][DD];
    const int b = blockIdx.x;
    const int t = threadIdx.x;
    const int ti = t >> 6, c = t & 63;
    const int i = b * 4 + ti;
    Es[ti][c] = g_E[(size_t)i * DD + c];
    const float alpha = __ldg(alpha_p);

    float acc = 0.f;
    for (int k = 0; k < KH; k++) {
        __syncthreads();
        #pragma unroll
        for (int q = 0; q < 16; q++) {
            int idx = t + 256 * q;
            Ms[idx >> 6][idx & 63] = g_M[(size_t)k * DD * DD + idx];
        }
        __syncthreads();
        float dotm = 0.f;
        #pragma unroll 8
        for (int c1 = 0; c1 < DD; c1++) dotm += Es[ti][c1] * Ms[c1][c];
        size_t idx = ((size_t)k * NN + i) * DD + c;
        float s = alpha * dotm;
        #pragma unroll
        for (int z = 0; z < SPLIT; z++)
            s += g_Cp[(size_t)z * (KH * NN * DD) + idx];
        acc += g_dinv[(size_t)k * NN + i] * s;
    }
    out[(size_t)i * DD + c] = fmaxf(acc, 0.f);
}

// ---------------- launch ----------------------------------------------------
extern "C" void kernel_launch(void* const* d_in, const int* in_sizes, int n_in,
                              void* d_out, int out_size) {
    const float* X     = (const float*)d_in[0];
    const float* A     = (const float*)d_in[1];
    const float* Wemb  = (const float*)d_in[2];
    const float* Whops = (const float*)d_in[3];
    const float* alpha = (const float*)d_in[4];
    float* out = (float*)d_out;

    cudaFuncSetAttribute(spmm_mma_kernel,
                         cudaFuncAttributeMaxDynamicSharedMemorySize, SPMM_SMEM);

    zero_kernel<<<48, 256>>>();
    proj_kernel<<<dim3(256, 4), 256>>>(X, Wemb, Whops);
    colsum_kernel<<<32, 256>>>();
    deg_kernel<<<KH * NN, 256>>>(A, alpha);
    prep_kernel<<<dim3(64, KH), 256>>>();
    mmat_kernel<<<dim3(64, KH), 256>>>();
    spmm_mma_kernel<<<dim3(32, KH, SPLIT), 256, SPMM_SMEM>>>(A);
    final_kernel<<<1024, 256>>>(alpha, out);
}

// round 10
// speedup vs baseline: 4.4548x; 1.0422x over previous
#include <cuda_runtime.h>
#include <cuda_bf16.h>
#include <math.h>
#include <cstdint>

#define NN 4096
#define FF 128
#define DD 64
#define KH 3
#define SPLIT 3
#define KCHUNK 32
#define NCHTOT (NN / KCHUNK)    // 128
#define CHSPL 43                // chunks per split (last gets 42)

// ---------------- scratch (device globals; no allocations allowed) ----------
__device__ float g_E[NN * DD];                 // X @ W_emb
__device__ float g_XW[KH * NN * DD];           // per-hop projections
// Yb: (d.*XW)^T, bf16 exact 2-term split, hi/lo interleaved per k-pair:
// word j (uint32) of row (k,n): j even -> hi bf16x2 of k=j,j+1 ; j odd -> lo
__device__ __align__(16) uint32_t g_Yb[KH * DD * NN];
__device__ float g_Cp[SPLIT * KH * NN * DD];   // partial C per K-split
__device__ float g_dinv[KH * NN];              // deg^{-1/2}
__device__ float g_S[DD];                      // colsum(E)
__device__ float g_M[KH * DD * DD];            // M_k = E^T @ Y_k

// ---------------- helpers ----------------------------------------------------
__device__ __forceinline__ uint32_t smem_u32(const void* p) {
    uint32_t a;
    asm("{ .reg .u64 t; cvta.to.shared.u64 t, %1; cvt.u32.u64 %0, t; }" : "=r"(a) : "l"(p));
    return a;
}
#define CP_ASYNC16(dst, src) \
    asm volatile("cp.async.cg.shared.global [%0], [%1], 16;" :: "r"(dst), "l"(src) : "memory")
#define CP_COMMIT() asm volatile("cp.async.commit_group;" ::: "memory")
#define CP_WAIT(n)  asm volatile("cp.async.wait_group %0;" :: "n"(n) : "memory")

// exact 2-term bf16 split of a float pair (x = low/even-k, y = high/odd-k)
__device__ __forceinline__ void split_bf16x2(float x, float y, uint32_t& h, uint32_t& l) {
    asm("cvt.rn.bf16x2.f32 %0, %1, %2;" : "=r"(h) : "f"(y), "f"(x));
    float hx = __uint_as_float(h << 16);
    float hy = __uint_as_float(h & 0xFFFF0000u);
    float lx = x - hx;
    float ly = y - hy;
    asm("cvt.rn.bf16x2.f32 %0, %1, %2;" : "=r"(l) : "f"(ly), "f"(lx));
}

__device__ __forceinline__ void mma_bf16(float* d, const uint32_t* a, const uint32_t* b) {
    asm volatile(
        "mma.sync.aligned.m16n8k16.row.col.f32.bf16.bf16.f32 "
        "{%0,%1,%2,%3}, {%4,%5,%6,%7}, {%8,%9}, {%0,%1,%2,%3};\n"
        : "+f"(d[0]), "+f"(d[1]), "+f"(d[2]), "+f"(d[3])
        : "r"(a[0]), "r"(a[1]), "r"(a[2]), "r"(a[3]), "r"(b[0]), "r"(b[1]));
}

// ---------------- zero the atomic accumulators ------------------------------
__global__ void zero_kernel() {
    int t = blockIdx.x * blockDim.x + threadIdx.x;
    if (t < DD) g_S[t] = 0.f;
    if (t < KH * DD * DD) g_M[t] = 0.f;
}

// ---------------- E = X @ W_emb, XW[k] = X @ W_hops[k] ----------------------
__global__ void proj_kernel(const float* __restrict__ X,
                            const float* __restrict__ Wemb,
                            const float* __restrict__ Whops) {
    __shared__ float Xs[16][FF + 1];
    const int rb = blockIdx.x;
    const int m = blockIdx.y;
    const float* W = (m == 0) ? Wemb : (Whops + (size_t)(m - 1) * FF * DD);
    float* Out = (m == 0) ? g_E : (g_XW + (size_t)(m - 1) * NN * DD);
    const int t = threadIdx.x;

    #pragma unroll
    for (int i = 0; i < 2; i++) {
        int idx = t + 256 * i;
        int row = idx >> 5;
        int c4 = idx & 31;
        float4 v = *reinterpret_cast<const float4*>(X + (size_t)(rb * 16 + row) * FF + c4 * 4);
        Xs[row][c4 * 4 + 0] = v.x; Xs[row][c4 * 4 + 1] = v.y;
        Xs[row][c4 * 4 + 2] = v.z; Xs[row][c4 * 4 + 3] = v.w;
    }
    __syncthreads();

    const int c = t & 63;
    const int rq = t >> 6;
    float acc[4] = {0.f, 0.f, 0.f, 0.f};
    for (int f = 0; f < FF; f++) {
        float w = __ldg(W + (size_t)f * DD + c);
        #pragma unroll
        for (int r = 0; r < 4; r++) acc[r] += Xs[rq * 4 + r][f] * w;
    }
    #pragma unroll
    for (int r = 0; r < 4; r++)
        Out[(size_t)(rb * 16 + rq * 4 + r) * DD + c] = acc[r];
}

// ---------------- S = colsum(E). grid 32, block 256 -------------------------
__global__ void colsum_kernel() {
    __shared__ float red[4][DD];
    const int t = threadIdx.x;
    const int b = blockIdx.x;
    const int c = t & 63, g = t >> 6;
    float acc = 0.f;
    for (int r = 0; r < 32; r++)
        acc += g_E[(size_t)(b * 128 + g * 32 + r) * DD + c];
    red[g][c] = acc;
    __syncthreads();
    if (t < DD)
        atomicAdd(&g_S[t], red[0][t] + red[1][t] + red[2][t] + red[3][t]);
}

// ---------------- dinv[k][i] = (rowsum(A_k)[i] + alpha*E[i].S)^(-1/2) -------
__global__ void deg_kernel(const float* __restrict__ A,
                           const float* __restrict__ alpha_p) {
    __shared__ float wsum[8];
    __shared__ float dsum[2];
    const int bid = blockIdx.x;           // k*NN + i
    const int i = bid & (NN - 1);
    const float* Arow = A + (size_t)bid * NN;
    const int t = threadIdx.x;

    float acc = 0.f;
    #pragma unroll
    for (int j = 0; j < 4; j++) {
        float4 v = *reinterpret_cast<const float4*>(Arow + (size_t)(t + 256 * j) * 4);
        acc += (v.x + v.y) + (v.z + v.w);
    }
    #pragma unroll
    for (int o = 16; o > 0; o >>= 1) acc += __shfl_down_sync(0xffffffffu, acc, o);
    if ((t & 31) == 0) wsum[t >> 5] = acc;
    __syncthreads();
    if (t < 64) {
        float p = g_E[(size_t)i * DD + t] * g_S[t];
        #pragma unroll
        for (int o = 16; o > 0; o >>= 1) p += __shfl_down_sync(0xffffffffu, p, o);
        if ((t & 31) == 0) dsum[t >> 5] = p;
    }
    __syncthreads();
    if (t == 0) {
        float rs = 0.f;
        #pragma unroll
        for (int w = 0; w < 8; w++) rs += wsum[w];
        float deg = rs + __ldg(alpha_p) * (dsum[0] + dsum[1]);
        g_dinv[bid] = 1.0f / sqrtf(deg);
    }
}

// ---------------- Yb[k][n][..] = split_bf16( dinv[k][j] * XW[k][j][n] ) -----
// grid (64, KH), block 256 — 64x64 transpose tiles. hi/lo interleaved.
__global__ void prep_kernel() {
    __shared__ float T[64][65];
    const int k = blockIdx.y;
    const int jb = blockIdx.x * 64;
    const int t = threadIdx.x;

    #pragma unroll
    for (int q = 0; q < 4; q++) {
        int idx = t + 256 * q;            // 1024 float4
        int r = idx >> 4;
        int c4 = idx & 15;
        float dv = g_dinv[(size_t)k * NN + jb + r];
        float4 v = *reinterpret_cast<const float4*>(g_XW + ((size_t)k * NN + jb + r) * DD + c4 * 4);
        T[r][c4 * 4 + 0] = v.x * dv;
        T[r][c4 * 4 + 1] = v.y * dv;
        T[r][c4 * 4 + 2] = v.z * dv;
        T[r][c4 * 4 + 3] = v.w * dv;
    }
    __syncthreads();

    const int n = t >> 2;
    const int jq = t & 3;
    const size_t base = ((size_t)k * DD + n) * NN + jb + jq * 16;
    #pragma unroll
    for (int m4 = 0; m4 < 4; m4++) {
        float y0 = T[jq * 16 + m4 * 4 + 0][n];
        float y1 = T[jq * 16 + m4 * 4 + 1][n];
        float y2 = T[jq * 16 + m4 * 4 + 2][n];
        float y3 = T[jq * 16 + m4 * 4 + 3][n];
        uint32_t h01, l01, h23, l23;
        split_bf16x2(y0, y1, h01, l01);
        split_bf16x2(y2, y3, h23, l23);
        *reinterpret_cast<uint4*>(g_Yb + base + m4 * 4) = make_uint4(h01, l01, h23, l23);
    }
}

// ---------------- M_k = E^T @ (d_k . XW_k)  (64x64 each) --------------------
__global__ void mmat_kernel() {
    __shared__ float Es[64][DD];
    __shared__ float Ys[64][DD];
    const int k = blockIdx.y;
    const int base = blockIdx.x * 64;
    const int t = threadIdx.x;

    #pragma unroll
    for (int i = 0; i < 4; i++) {
        int idx = t + 256 * i;
        int row = idx >> 4;
        int c4 = idx & 15;
        float4 e = *reinterpret_cast<const float4*>(g_E + (size_t)(base + row) * DD + c4 * 4);
        *reinterpret_cast<float4*>(&Es[row][c4 * 4]) = e;
        float dv = g_dinv[(size_t)k * NN + base + row];
        float4 xw = *reinterpret_cast<const float4*>(g_XW + ((size_t)k * NN + base + row) * DD + c4 * 4);
        xw.x *= dv; xw.y *= dv; xw.z *= dv; xw.w *= dv;
        *reinterpret_cast<float4*>(&Ys[row][c4 * 4]) = xw;
    }
    __syncthreads();

    const int t1 = t >> 4, t2 = t & 15;
    float acc[4][4] = {};
    for (int j = 0; j < 64; j++) {
        float4 e = *reinterpret_cast<const float4*>(&Es[j][t1 * 4]);
        float4 y = *reinterpret_cast<const float4*>(&Ys[j][t2 * 4]);
        float ea[4] = {e.x, e.y, e.z, e.w};
        float ya[4] = {y.x, y.y, y.z, y.w};
        #pragma unroll
        for (int a = 0; a < 4; a++)
            #pragma unroll
            for (int b = 0; b < 4; b++) acc[a][b] += ea[a] * ya[b];
    }
    #pragma unroll
    for (int a = 0; a < 4; a++)
        #pragma unroll
        for (int b = 0; b < 4; b++)
            atomicAdd(&g_M[(size_t)k * DD * DD + (t1 * 4 + a) * DD + t2 * 4 + b], acc[a][b]);
}

// ---------------- C_k = A_k @ Y_k via mma.sync bf16 m16n8k16 (3-MMA split) --
// grid (32, KH, 3), block 256 (8 warps, warp tile 32x32). One full wave.
// A staged f32 (split to bf16 hi/lo in registers), pair-rotated, conflict-free.
// B staged pre-split interleaved bf16 (hi/lo per pair adjacent -> LDS.64),
// 16B-group rotation by row parity (store conflict-free, loads 2-way).
#define A_STAGE 16384                         // 128*32*4
#define B_STAGE 8192                          // 64*32 words *4B
#define STAGE_BYTES (A_STAGE + B_STAGE)       // 24576
#define SPMM_SMEM (2 * STAGE_BYTES)           // 49152

__global__ void __launch_bounds__(256, 2) spmm_mma_kernel(const float* __restrict__ A) {
    extern __shared__ char smem[];
    const uint32_t sb = smem_u32(smem);
    const int t = threadIdx.x;
    const int wid = t >> 5;
    const int lid = t & 31;
    const int g = lid >> 2;                // 0..7
    const int tig = lid & 3;               // 0..3
    const int warpM = wid >> 1;            // 0..3
    const int warpN = wid & 1;             // 0..1
    const int k = blockIdx.y;
    const int r0 = blockIdx.x * 128;
    const int kz = blockIdx.z;
    const int ch0 = kz * CHSPL;
    const int nch = (kz == SPLIT - 1) ? (NCHTOT - ch0) : CHSPL;  // 43/43/42
    const size_t k0 = (size_t)ch0 * KCHUNK;

    // ---- fill geometry ----
    uint32_t adst[4];
    const float* asrc[4];
    #pragma unroll
    for (int q = 0; q < 4; q++) {
        int idx = t + 256 * q;
        int row = idx >> 3;                // 0..127
        int c4 = idx & 7;                  // 16B unit -> pairs 2c4, 2c4+1
        adst[q] = (uint32_t)(row * 128 + 8 * ((2 * c4 + 4 * (row & 3)) & 15));
        asrc[q] = A + ((size_t)k * NN + r0 + row) * NN + k0 + c4 * 4;
    }
    uint32_t bdst[2];
    const uint32_t* bsrc[2];
    #pragma unroll
    for (int q = 0; q < 2; q++) {
        int idx = t + 256 * q;             // 512 groups = 64 rows x 8
        int row = idx >> 3;                // 0..63
        int c8 = idx & 7;                  // 16B group (4 words)
        bdst[q] = (uint32_t)(A_STAGE + row * 128 + 16 * ((c8 + 4 * (row & 1)) & 7));
        bsrc[q] = g_Yb + ((size_t)k * DD + row) * NN + k0 + c8 * 4;
    }

    float acc[2][4][4];
    #pragma unroll
    for (int mt = 0; mt < 2; mt++)
        #pragma unroll
        for (int nt = 0; nt < 4; nt++)
            #pragma unroll
            for (int r = 0; r < 4; r++) acc[mt][nt][r] = 0.f;

    // issue chunk 0
    {
        #pragma unroll
        for (int q = 0; q < 4; q++) CP_ASYNC16(sb + adst[q], asrc[q]);
        #pragma unroll
        for (int q = 0; q < 2; q++) CP_ASYNC16(sb + bdst[q], bsrc[q]);
        CP_COMMIT();
    }

    for (int i = 0; i < nch; i++) {
        const int st = i & 1;
        if (i + 1 < nch) {
            const uint32_t soff = sb + ((i + 1) & 1) * STAGE_BYTES;
            const int kb = (i + 1) * KCHUNK;
            #pragma unroll
            for (int q = 0; q < 4; q++) CP_ASYNC16(soff + adst[q], asrc[q] + kb);
            #pragma unroll
            for (int q = 0; q < 2; q++) CP_ASYNC16(soff + bdst[q], bsrc[q] + kb);
            CP_COMMIT();
            CP_WAIT(1);
        } else {
            CP_WAIT(0);
        }
        __syncthreads();

        const float* sA = reinterpret_cast<const float*>(smem + st * STAGE_BYTES);
        const uint2* sB2 = reinterpret_cast<const uint2*>(smem + st * STAGE_BYTES + A_STAGE);

        #pragma unroll
        for (int kb16 = 0; kb16 < 2; kb16++) {
            const int p0 = kb16 * 8;

            // A fragments: LDS.64 + in-register bf16 split
            uint32_t ah[2][4], al[2][4];
            const int rotA = 4 * (g & 3);
            const int cA0 = 2 * ((p0 + tig + rotA) & 15);
            const int cA2 = 2 * ((p0 + tig + 4 + rotA) & 15);
            #pragma unroll
            for (int mt = 0; mt < 2; mt++) {
                const int ra = warpM * 32 + mt * 16 + g;
                const int rb = ra + 8;
                float2 x0 = *reinterpret_cast<const float2*>(sA + ra * 32 + cA0);
                float2 x1 = *reinterpret_cast<const float2*>(sA + rb * 32 + cA0);
                float2 x2 = *reinterpret_cast<const float2*>(sA + ra * 32 + cA2);
                float2 x3 = *reinterpret_cast<const float2*>(sA + rb * 32 + cA2);
                split_bf16x2(x0.x, x0.y, ah[mt][0], al[mt][0]);
                split_bf16x2(x1.x, x1.y, ah[mt][1], al[mt][1]);
                split_bf16x2(x2.x, x2.y, ah[mt][2], al[mt][2]);
                split_bf16x2(x3.x, x3.y, ah[mt][3], al[mt][3]);
            }

            // B fragments: LDS.64 -> (hi, lo) together
            uint32_t bh[4][2], bl[4][2];
            const int gp1 = kb16 * 4 + (tig >> 1);   // logical 16B group of pair p0+tig
            const int slot = tig & 1;
            #pragma unroll
            for (int nt = 0; nt < 4; nt++) {
                const int rn_ = warpN * 32 + nt * 8 + g;
                const int rrot = 4 * (rn_ & 1);
                const int u0 = rn_ * 16 + 2 * ((gp1 + rrot) & 7) + slot;
                const int u1 = rn_ * 16 + 2 * ((gp1 + 2 + rrot) & 7) + slot;
                uint2 v0 = sB2[u0];
                uint2 v1 = sB2[u1];
                bh[nt][0] = v0.x; bl[nt][0] = v0.y;
                bh[nt][1] = v1.x; bl[nt][1] = v1.y;
            }

            #pragma unroll
            for (int mt = 0; mt < 2; mt++)
                #pragma unroll
                for (int nt = 0; nt < 4; nt++) {
                    mma_bf16(acc[mt][nt], ah[mt], bh[nt]);
                    mma_bf16(acc[mt][nt], ah[mt], bl[nt]);
                    mma_bf16(acc[mt][nt], al[mt], bh[nt]);
                }
        }
        __syncthreads();
    }

    // ---- epilogue: write partial C ----
    float* Cb = g_Cp + ((size_t)kz * KH + k) * NN * DD + (size_t)r0 * DD;
    #pragma unroll
    for (int mt = 0; mt < 2; mt++) {
        const int row = warpM * 32 + mt * 16 + g;
        #pragma unroll
        for (int nt = 0; nt < 4; nt++) {
            const int col = warpN * 32 + nt * 8 + 2 * tig;
            *reinterpret_cast<float2*>(Cb + (size_t)row * DD + col) =
                make_float2(acc[mt][nt][0], acc[mt][nt][1]);
            *reinterpret_cast<float2*>(Cb + (size_t)(row + 8) * DD + col) =
                make_float2(acc[mt][nt][2], acc[mt][nt][3]);
        }
    }
}

// ---------------- out = relu( sum_k dinv_k[i] * (sum_z Cp + alpha*E@M_k) ) --
__global__ void final_kernel(const float* __restrict__ alpha_p,
                             float* __restrict__ out) {
    __shared__ float Ms[DD][DD];
    __shared__ float Es[4][DD];
    const int b = blockIdx.x;
    const int t = threadIdx.x;
    const int ti = t >> 6, c = t & 63;
    const int i = b * 4 + ti;
    Es[ti][c] = g_E[(size_t)i * DD + c];
    const float alpha = __ldg(alpha_p);

    float acc = 0.f;
    for (int k = 0; k < KH; k++) {
        __syncthreads();
        #pragma unroll
        for (int q = 0; q < 16; q++) {
            int idx = t + 256 * q;
            Ms[idx >> 6][idx & 63] = g_M[(size_t)k * DD * DD + idx];
        }
        __syncthreads();
        float dotm = 0.f;
        #pragma unroll 8
        for (int c1 = 0; c1 < DD; c1++) dotm += Es[ti][c1] * Ms[c1][c];
        size_t idx = ((size_t)k * NN + i) * DD + c;
        float s = alpha * dotm;
        #pragma unroll
        for (int z = 0; z < SPLIT; z++)
            s += g_Cp[(size_t)z * (KH * NN * DD) + idx];
        acc += g_dinv[(size_t)k * NN + i] * s;
    }
    out[(size_t)i * DD + c] = fmaxf(acc, 0.f);
}

// ---------------- launch ----------------------------------------------------
extern "C" void kernel_launch(void* const* d_in, const int* in_sizes, int n_in,
                              void* d_out, int out_size) {
    const float* X     = (const float*)d_in[0];
    const float* A     = (const float*)d_in[1];
    const float* Wemb  = (const float*)d_in[2];
    const float* Whops = (const float*)d_in[3];
    const float* alpha = (const float*)d_in[4];
    float* out = (float*)d_out;

    cudaFuncSetAttribute(spmm_mma_kernel,
                         cudaFuncAttributeMaxDynamicSharedMemorySize, SPMM_SMEM);

    zero_kernel<<<48, 256>>>();
    proj_kernel<<<dim3(256, 4), 256>>>(X, Wemb, Whops);
    colsum_kernel<<<32, 256>>>();
    deg_kernel<<<KH * NN, 256>>>(A, alpha);
    prep_kernel<<<dim3(64, KH), 256>>>();
    mmat_kernel<<<dim3(64, KH), 256>>>();
    spmm_mma_kernel<<<dim3(32, KH, SPLIT), 256, SPMM_SMEM>>>(A);
    final_kernel<<<1024, 256>>>(alpha, out);
}

// round 11
// speedup vs baseline: 5.0850x; 1.1415x over previous
#include <cuda_runtime.h>
#include <cuda_fp16.h>
#include <math.h>
#include <cstdint>

#define NN 4096
#define FF 128
#define DD 64
#define KH 3
#define SPLIT 3
#define KCHUNK 32
#define NCHTOT (NN / KCHUNK)    // 128
#define CHSPL 43                // chunks per split (last gets 42)

// ---------------- scratch (device globals; no allocations allowed) ----------
__device__ float g_E[NN * DD];                 // X @ W_emb
__device__ float g_XW[KH * NN * DD];           // per-hop projections
__device__ __align__(16) __half g_Yh[KH * DD * NN];  // (d.*XW)^T fp16
__device__ float g_Cp[SPLIT * KH * NN * DD];   // partial C per K-split
__device__ float g_dinv[KH * NN];              // deg^{-1/2}
__device__ float g_S[DD];                      // colsum(E)
__device__ float g_M[KH * DD * DD];            // M_k = E^T @ Y_k

// ---------------- helpers ----------------------------------------------------
__device__ __forceinline__ uint32_t smem_u32(const void* p) {
    uint32_t a;
    asm("{ .reg .u64 t; cvta.to.shared.u64 t, %1; cvt.u32.u64 %0, t; }" : "=r"(a) : "l"(p));
    return a;
}
#define CP_ASYNC16(dst, src) \
    asm volatile("cp.async.cg.shared.global [%0], [%1], 16;" :: "r"(dst), "l"(src) : "memory")
#define CP_COMMIT() asm volatile("cp.async.commit_group;" ::: "memory")
#define CP_WAIT(n)  asm volatile("cp.async.wait_group %0;" :: "n"(n) : "memory")

// pack two floats (x = even-k, y = odd-k) into fp16x2
__device__ __forceinline__ uint32_t f16x2(float x, float y) {
    uint32_t w;
    asm("cvt.rn.f16x2.f32 %0, %1, %2;" : "=r"(w) : "f"(y), "f"(x));
    return w;
}

__device__ __forceinline__ void mma_f16(float* d, const uint32_t* a, const uint32_t* b) {
    asm volatile(
        "mma.sync.aligned.m16n8k16.row.col.f32.f16.f16.f32 "
        "{%0,%1,%2,%3}, {%4,%5,%6,%7}, {%8,%9}, {%0,%1,%2,%3};\n"
        : "+f"(d[0]), "+f"(d[1]), "+f"(d[2]), "+f"(d[3])
        : "r"(a[0]), "r"(a[1]), "r"(a[2]), "r"(a[3]), "r"(b[0]), "r"(b[1]));
}

// ---------------- zero the atomic accumulators ------------------------------
__global__ void zero_kernel() {
    int t = blockIdx.x * blockDim.x + threadIdx.x;
    if (t < DD) g_S[t] = 0.f;
    if (t < KH * DD * DD) g_M[t] = 0.f;
}

// ---------------- E = X @ W_emb, XW[k] = X @ W_hops[k] ----------------------
__global__ void proj_kernel(const float* __restrict__ X,
                            const float* __restrict__ Wemb,
                            const float* __restrict__ Whops) {
    __shared__ float Xs[16][FF + 1];
    const int rb = blockIdx.x;
    const int m = blockIdx.y;
    const float* W = (m == 0) ? Wemb : (Whops + (size_t)(m - 1) * FF * DD);
    float* Out = (m == 0) ? g_E : (g_XW + (size_t)(m - 1) * NN * DD);
    const int t = threadIdx.x;

    #pragma unroll
    for (int i = 0; i < 2; i++) {
        int idx = t + 256 * i;
        int row = idx >> 5;
        int c4 = idx & 31;
        float4 v = *reinterpret_cast<const float4*>(X + (size_t)(rb * 16 + row) * FF + c4 * 4);
        Xs[row][c4 * 4 + 0] = v.x; Xs[row][c4 * 4 + 1] = v.y;
        Xs[row][c4 * 4 + 2] = v.z; Xs[row][c4 * 4 + 3] = v.w;
    }
    __syncthreads();

    const int c = t & 63;
    const int rq = t >> 6;
    float acc[4] = {0.f, 0.f, 0.f, 0.f};
    for (int f = 0; f < FF; f++) {
        float w = __ldg(W + (size_t)f * DD + c);
        #pragma unroll
        for (int r = 0; r < 4; r++) acc[r] += Xs[rq * 4 + r][f] * w;
    }
    #pragma unroll
    for (int r = 0; r < 4; r++)
        Out[(size_t)(rb * 16 + rq * 4 + r) * DD + c] = acc[r];
}

// ---------------- S = colsum(E). grid 32, block 256 -------------------------
__global__ void colsum_kernel() {
    __shared__ float red[4][DD];
    const int t = threadIdx.x;
    const int b = blockIdx.x;
    const int c = t & 63, g = t >> 6;
    float acc = 0.f;
    for (int r = 0; r < 32; r++)
        acc += g_E[(size_t)(b * 128 + g * 32 + r) * DD + c];
    red[g][c] = acc;
    __syncthreads();
    if (t < DD)
        atomicAdd(&g_S[t], red[0][t] + red[1][t] + red[2][t] + red[3][t]);
}

// ---------------- dinv[k][i] = (rowsum(A_k)[i] + alpha*E[i].S)^(-1/2) -------
__global__ void deg_kernel(const float* __restrict__ A,
                           const float* __restrict__ alpha_p) {
    __shared__ float wsum[8];
    __shared__ float dsum[2];
    const int bid = blockIdx.x;           // k*NN + i
    const int i = bid & (NN - 1);
    const float* Arow = A + (size_t)bid * NN;
    const int t = threadIdx.x;

    float acc = 0.f;
    #pragma unroll
    for (int j = 0; j < 4; j++) {
        float4 v = *reinterpret_cast<const float4*>(Arow + (size_t)(t + 256 * j) * 4);
        acc += (v.x + v.y) + (v.z + v.w);
    }
    #pragma unroll
    for (int o = 16; o > 0; o >>= 1) acc += __shfl_down_sync(0xffffffffu, acc, o);
    if ((t & 31) == 0) wsum[t >> 5] = acc;
    __syncthreads();
    if (t < 64) {
        float p = g_E[(size_t)i * DD + t] * g_S[t];
        #pragma unroll
        for (int o = 16; o > 0; o >>= 1) p += __shfl_down_sync(0xffffffffu, p, o);
        if ((t & 31) == 0) dsum[t >> 5] = p;
    }
    __syncthreads();
    if (t == 0) {
        float rs = 0.f;
        #pragma unroll
        for (int w = 0; w < 8; w++) rs += wsum[w];
        float deg = rs + __ldg(alpha_p) * (dsum[0] + dsum[1]);
        g_dinv[bid] = 1.0f / sqrtf(deg);
    }
}

// ---------------- Yh[k][n][j] = fp16( dinv[k][j] * XW[k][j][n] ) ------------
// grid (64, KH), block 256 — 64x64 transpose tiles.
__global__ void prep_kernel() {
    __shared__ float T[64][65];
    const int k = blockIdx.y;
    const int jb = blockIdx.x * 64;
    const int t = threadIdx.x;

    #pragma unroll
    for (int q = 0; q < 4; q++) {
        int idx = t + 256 * q;            // 1024 float4
        int r = idx >> 4;
        int c4 = idx & 15;
        float dv = g_dinv[(size_t)k * NN + jb + r];
        float4 v = *reinterpret_cast<const float4*>(g_XW + ((size_t)k * NN + jb + r) * DD + c4 * 4);
        T[r][c4 * 4 + 0] = v.x * dv;
        T[r][c4 * 4 + 1] = v.y * dv;
        T[r][c4 * 4 + 2] = v.z * dv;
        T[r][c4 * 4 + 3] = v.w * dv;
    }
    __syncthreads();

    const int n = t >> 2;
    const int jq = t & 3;
    const size_t base = ((size_t)k * DD + n) * NN + jb + jq * 16;
    uint32_t w[8];
    #pragma unroll
    for (int m4 = 0; m4 < 4; m4++) {
        w[2 * m4 + 0] = f16x2(T[jq * 16 + m4 * 4 + 0][n], T[jq * 16 + m4 * 4 + 1][n]);
        w[2 * m4 + 1] = f16x2(T[jq * 16 + m4 * 4 + 2][n], T[jq * 16 + m4 * 4 + 3][n]);
    }
    *reinterpret_cast<uint4*>(g_Yh + base)     = make_uint4(w[0], w[1], w[2], w[3]);
    *reinterpret_cast<uint4*>(g_Yh + base + 8) = make_uint4(w[4], w[5], w[6], w[7]);
}

// ---------------- M_k = E^T @ (d_k . XW_k)  (64x64 each) --------------------
__global__ void mmat_kernel() {
    __shared__ float Es[64][DD];
    __shared__ float Ys[64][DD];
    const int k = blockIdx.y;
    const int base = blockIdx.x * 64;
    const int t = threadIdx.x;

    #pragma unroll
    for (int i = 0; i < 4; i++) {
        int idx = t + 256 * i;
        int row = idx >> 4;
        int c4 = idx & 15;
        float4 e = *reinterpret_cast<const float4*>(g_E + (size_t)(base + row) * DD + c4 * 4);
        *reinterpret_cast<float4*>(&Es[row][c4 * 4]) = e;
        float dv = g_dinv[(size_t)k * NN + base + row];
        float4 xw = *reinterpret_cast<const float4*>(g_XW + ((size_t)k * NN + base + row) * DD + c4 * 4);
        xw.x *= dv; xw.y *= dv; xw.z *= dv; xw.w *= dv;
        *reinterpret_cast<float4*>(&Ys[row][c4 * 4]) = xw;
    }
    __syncthreads();

    const int t1 = t >> 4, t2 = t & 15;
    float acc[4][4] = {};
    for (int j = 0; j < 64; j++) {
        float4 e = *reinterpret_cast<const float4*>(&Es[j][t1 * 4]);
        float4 y = *reinterpret_cast<const float4*>(&Ys[j][t2 * 4]);
        float ea[4] = {e.x, e.y, e.z, e.w};
        float ya[4] = {y.x, y.y, y.z, y.w};
        #pragma unroll
        for (int a = 0; a < 4; a++)
            #pragma unroll
            for (int b = 0; b < 4; b++) acc[a][b] += ea[a] * ya[b];
    }
    #pragma unroll
    for (int a = 0; a < 4; a++)
        #pragma unroll
        for (int b = 0; b < 4; b++)
            atomicAdd(&g_M[(size_t)k * DD * DD + (t1 * 4 + a) * DD + t2 * 4 + b], acc[a][b]);
}

// ---------------- C_k = A_k @ Y_k via mma.sync fp16 m16n8k16 (single MMA) ---
// grid (32, KH, 3), block 256 (8 warps, warp tile 32x32). One full wave.
// A staged f32 (converted to fp16x2 in registers), pair-rotated, conflict-free.
// B staged fp16 (pre-converted in prep), word rotation by row (2-way loads ok).
#define A_STAGE 16384                         // 128*32*4
#define B_STAGE 4096                          // 64*32*2
#define STAGE_BYTES (A_STAGE + B_STAGE)       // 20480
#define SPMM_SMEM (2 * STAGE_BYTES)           // 40960

__global__ void __launch_bounds__(256, 2) spmm_mma_kernel(const float* __restrict__ A) {
    extern __shared__ char smem[];
    const uint32_t sb = smem_u32(smem);
    const int t = threadIdx.x;
    const int wid = t >> 5;
    const int lid = t & 31;
    const int g = lid >> 2;                // 0..7
    const int tig = lid & 3;               // 0..3
    const int warpM = wid >> 1;            // 0..3
    const int warpN = wid & 1;             // 0..1
    const int k = blockIdx.y;
    const int r0 = blockIdx.x * 128;
    const int kz = blockIdx.z;
    const int ch0 = kz * CHSPL;
    const int nch = (kz == SPLIT - 1) ? (NCHTOT - ch0) : CHSPL;  // 43/43/42
    const size_t k0 = (size_t)ch0 * KCHUNK;

    // ---- fill geometry ----
    uint32_t adst[4];
    const float* asrc[4];
    #pragma unroll
    for (int q = 0; q < 4; q++) {
        int idx = t + 256 * q;
        int row = idx >> 3;                // 0..127
        int c4 = idx & 7;                  // 16B unit -> pairs 2c4, 2c4+1
        adst[q] = (uint32_t)(row * 128 + 8 * ((2 * c4 + 4 * (row & 3)) & 15));
        asrc[q] = A + ((size_t)k * NN + r0 + row) * NN + k0 + c4 * 4;
    }
    uint32_t bdst;
    const __half* bsrc;
    {
        int row = t >> 2;                  // 0..63
        int c4 = t & 3;                    // 16B unit = 4 words = 8 halves
        bdst = (uint32_t)(A_STAGE + row * 64 + 4 * ((4 * c4 + 4 * (row & 3)) & 15));
        bsrc = g_Yh + ((size_t)k * DD + row) * NN + k0 + c4 * 8;
    }

    float acc[2][4][4];
    #pragma unroll
    for (int mt = 0; mt < 2; mt++)
        #pragma unroll
        for (int nt = 0; nt < 4; nt++)
            #pragma unroll
            for (int r = 0; r < 4; r++) acc[mt][nt][r] = 0.f;

    // issue chunk 0
    {
        #pragma unroll
        for (int q = 0; q < 4; q++) CP_ASYNC16(sb + adst[q], asrc[q]);
        CP_ASYNC16(sb + bdst, bsrc);
        CP_COMMIT();
    }

    for (int i = 0; i < nch; i++) {
        const int st = i & 1;
        if (i + 1 < nch) {
            const uint32_t soff = sb + ((i + 1) & 1) * STAGE_BYTES;
            const int kb = (i + 1) * KCHUNK;
            #pragma unroll
            for (int q = 0; q < 4; q++) CP_ASYNC16(soff + adst[q], asrc[q] + kb);
            CP_ASYNC16(soff + bdst, bsrc + kb);
            CP_COMMIT();
            CP_WAIT(1);
        } else {
            CP_WAIT(0);
        }
        __syncthreads();

        const float* sA = reinterpret_cast<const float*>(smem + st * STAGE_BYTES);
        const uint32_t* sB = reinterpret_cast<const uint32_t*>(smem + st * STAGE_BYTES + A_STAGE);

        #pragma unroll
        for (int kb16 = 0; kb16 < 2; kb16++) {
            const int p0 = kb16 * 8;

            // A fragments: LDS.64 + in-register fp16x2 convert
            uint32_t af[2][4];
            const int rotA = 4 * (g & 3);
            const int cA0 = 2 * ((p0 + tig + rotA) & 15);
            const int cA2 = 2 * ((p0 + tig + 4 + rotA) & 15);
            #pragma unroll
            for (int mt = 0; mt < 2; mt++) {
                const int ra = warpM * 32 + mt * 16 + g;
                const int rb = ra + 8;
                float2 x0 = *reinterpret_cast<const float2*>(sA + ra * 32 + cA0);
                float2 x1 = *reinterpret_cast<const float2*>(sA + rb * 32 + cA0);
                float2 x2 = *reinterpret_cast<const float2*>(sA + ra * 32 + cA2);
                float2 x3 = *reinterpret_cast<const float2*>(sA + rb * 32 + cA2);
                af[mt][0] = f16x2(x0.x, x0.y);
                af[mt][1] = f16x2(x1.x, x1.y);
                af[mt][2] = f16x2(x2.x, x2.y);
                af[mt][3] = f16x2(x3.x, x3.y);
            }

            // B fragments: LDS.32 of fp16x2 words (rotated layout)
            uint32_t bf[4][2];
            #pragma unroll
            for (int nt = 0; nt < 4; nt++) {
                const int n_ = warpN * 32 + nt * 8 + g;
                const int rot = 4 * (n_ & 3);
                bf[nt][0] = sB[n_ * 16 + ((p0 + tig + rot) & 15)];
                bf[nt][1] = sB[n_ * 16 + ((p0 + tig + 4 + rot) & 15)];
            }

            #pragma unroll
            for (int mt = 0; mt < 2; mt++)
                #pragma unroll
                for (int nt = 0; nt < 4; nt++)
                    mma_f16(acc[mt][nt], af[mt], bf[nt]);
        }
        __syncthreads();
    }

    // ---- epilogue: write partial C ----
    float* Cb = g_Cp + ((size_t)kz * KH + k) * NN * DD + (size_t)r0 * DD;
    #pragma unroll
    for (int mt = 0; mt < 2; mt++) {
        const int row = warpM * 32 + mt * 16 + g;
        #pragma unroll
        for (int nt = 0; nt < 4; nt++) {
            const int col = warpN * 32 + nt * 8 + 2 * tig;
            *reinterpret_cast<float2*>(Cb + (size_t)row * DD + col) =
                make_float2(acc[mt][nt][0], acc[mt][nt][1]);
            *reinterpret_cast<float2*>(Cb + (size_t)(row + 8) * DD + col) =
                make_float2(acc[mt][nt][2], acc[mt][nt][3]);
        }
    }
}

// ---------------- out = relu( sum_k dinv_k[i] * (sum_z Cp + alpha*E@M_k) ) --
__global__ void final_kernel(const float* __restrict__ alpha_p,
                             float* __restrict__ out) {
    __shared__ float Ms[DD][DD];
    __shared__ float Es[4][DD];
    const int b = blockIdx.x;
    const int t = threadIdx.x;
    const int ti = t >> 6, c = t & 63;
    const int i = b * 4 + ti;
    Es[ti][c] = g_E[(size_t)i * DD + c];
    const float alpha = __ldg(alpha_p);

    float acc = 0.f;
    for (int k = 0; k < KH; k++) {
        __syncthreads();
        #pragma unroll
        for (int q = 0; q < 16; q++) {
            int idx = t + 256 * q;
            Ms[idx >> 6][idx & 63] = g_M[(size_t)k * DD * DD + idx];
        }
        __syncthreads();
        float dotm = 0.f;
        #pragma unroll 8
        for (int c1 = 0; c1 < DD; c1++) dotm += Es[ti][c1] * Ms[c1][c];
        size_t idx = ((size_t)k * NN + i) * DD + c;
        float s = alpha * dotm;
        #pragma unroll
        for (int z = 0; z < SPLIT; z++)
            s += g_Cp[(size_t)z * (KH * NN * DD) + idx];
        acc += g_dinv[(size_t)k * NN + i] * s;
    }
    out[(size_t)i * DD + c] = fmaxf(acc, 0.f);
}

// ---------------- launch ----------------------------------------------------
extern "C" void kernel_launch(void* const* d_in, const int* in_sizes, int n_in,
                              void* d_out, int out_size) {
    const float* X     = (const float*)d_in[0];
    const float* A     = (const float*)d_in[1];
    const float* Wemb  = (const float*)d_in[2];
    const float* Whops = (const float*)d_in[3];
    const float* alpha = (const float*)d_in[4];
    float* out = (float*)d_out;

    cudaFuncSetAttribute(spmm_mma_kernel,
                         cudaFuncAttributeMaxDynamicSharedMemorySize, SPMM_SMEM);

    zero_kernel<<<48, 256>>>();
    proj_kernel<<<dim3(256, 4), 256>>>(X, Wemb, Whops);
    colsum_kernel<<<32, 256>>>();
    deg_kernel<<<KH * NN, 256>>>(A, alpha);
    prep_kernel<<<dim3(64, KH), 256>>>();
    mmat_kernel<<<dim3(64, KH), 256>>>();
    spmm_mma_kernel<<<dim3(32, KH, SPLIT), 256, SPMM_SMEM>>>(A);
    final_kernel<<<1024, 256>>>(alpha, out);
}